// round 12
// baseline (speedup 1.0000x reference)
#include <cuda_runtime.h>
#include <cstdint>

// Problem constants (ShowAndTell GRU decoder)
#define BB 128        // batch
#define TT 31         // decode steps (T-1)
#define EE 300        // embed dim
#define HH 512        // hidden
#define VV 32000      // vocab
#define G3 1536       // 3*H

// Scratch (static device globals; no allocation allowed)
__device__ float d_Hseq[32 * BB * HH];        // h_0 .. h_31   [t][b][h]
__device__ float d_GI[TT * BB * G3];          // input gates   [(t*B+b)][3H]

// ---------- PTX helpers (base-target safe: sm_80+ features only) ----------
static __device__ __forceinline__ float tf32r(float x) {
    uint32_t u;
    asm("cvt.rna.tf32.f32 %0, %1;" : "=r"(u) : "f"(x));
    return __uint_as_float(u);
}
// m16n8k8 tf32 MMA (legacy HMMA path; supported on base sm_103 target)
static __device__ __forceinline__ void mma8(float* c, const uint32_t* a, const uint32_t* b) {
    asm volatile(
        "mma.sync.aligned.m16n8k8.row.col.f32.tf32.tf32.f32 "
        "{%0,%1,%2,%3}, {%4,%5,%6,%7}, {%8,%9}, {%0,%1,%2,%3};"
        : "+f"(c[0]), "+f"(c[1]), "+f"(c[2]), "+f"(c[3])
        : "r"(a[0]), "r"(a[1]), "r"(a[2]), "r"(a[3]), "r"(b[0]), "r"(b[1]));
}

// ---------- packed f32x2 helpers (FFMA2 path; proven on this toolchain) ----------
static __device__ __forceinline__ unsigned long long pk2(float a) {
    unsigned long long r;
    asm("mov.b64 %0, {%1, %1};" : "=l"(r) : "f"(a));
    return r;
}
static __device__ __forceinline__ void ffma2(unsigned long long &c,
                                             unsigned long long a,
                                             unsigned long long b) {
    asm("fma.rn.f32x2 %0, %1, %2, %0;" : "+l"(c) : "l"(a), "l"(b));
}
static __device__ __forceinline__ float2 up2(unsigned long long v) {
    float2 f;
    asm("mov.b64 {%0, %1}, %2;" : "=f"(f.x), "=f"(f.y) : "l"(v));
    return f;
}

// ---------------------------------------------------------------------------
// Kernel 1: hidden0 = relu(concat(g,t) @ W_feat + b_feat)   -> d_Hseq[0]
// ---------------------------------------------------------------------------
__global__ void k_feat(const float* __restrict__ g, const float* __restrict__ t,
                       const float* __restrict__ Wf, const float* __restrict__ bf) {
    __shared__ float sg[128], st[128];
    int b = blockIdx.y;
    int j = blockIdx.x * 256 + threadIdx.x;
    if (threadIdx.x < 128) {
        sg[threadIdx.x] = g[b * 128 + threadIdx.x];
        st[threadIdx.x] = t[b * 128 + threadIdx.x];
    }
    __syncthreads();
    float acc = bf[j];
#pragma unroll 4
    for (int k = 0; k < 128; k++) acc += sg[k] * Wf[k * HH + j];
#pragma unroll 4
    for (int k = 0; k < 128; k++) acc += st[k] * Wf[(128 + k) * HH + j];
    d_Hseq[b * HH + j] = fmaxf(acc, 0.f);
}

// ---------------------------------------------------------------------------
// Kernel 2: GI = X @ W_ih^T + b_ih (all timesteps, no recurrence)
// ---------------------------------------------------------------------------
__global__ __launch_bounds__(256, 2) void k_gi(const float* __restrict__ lf,
                                               const float* __restrict__ Wih,
                                               const float* __restrict__ bih) {
    __shared__ float As[16][132];
    __shared__ float Bs[16][132];
    int tid = threadIdx.x;
    int tx = tid & 15, ty = tid >> 4;
    int n0 = blockIdx.x * 128;
    int ts = blockIdx.y;

    unsigned long long acc[8][4];
#pragma unroll
    for (int i = 0; i < 8; i++)
#pragma unroll
        for (int j = 0; j < 4; j++) acc[i][j] = 0ull;

    int lr = tid >> 2;
    int lk = (tid & 3) * 4;

#pragma unroll 1
    for (int k0 = 0; k0 < EE; k0 += 16) {
        bool kok = (k0 + lk) < EE;
#pragma unroll
        for (int p = 0; p < 2; p++) {
            int r = lr + p * 64;
            float4 v = make_float4(0.f, 0.f, 0.f, 0.f);
            float4 w = make_float4(0.f, 0.f, 0.f, 0.f);
            if (kok) {
                v = *(const float4*)&lf[(size_t)(r * 32 + ts) * EE + k0 + lk];
                w = *(const float4*)&Wih[(size_t)(n0 + r) * EE + k0 + lk];
            }
            As[lk + 0][r] = v.x; As[lk + 1][r] = v.y; As[lk + 2][r] = v.z; As[lk + 3][r] = v.w;
            Bs[lk + 0][r] = w.x; Bs[lk + 1][r] = w.y; Bs[lk + 2][r] = w.z; Bs[lk + 3][r] = w.w;
        }
        __syncthreads();
#pragma unroll
        for (int k = 0; k < 16; k++) {
            float4 a0 = *(const float4*)&As[k][ty * 8];
            float4 a1 = *(const float4*)&As[k][ty * 8 + 4];
            ulonglong2 q0 = *(const ulonglong2*)&Bs[k][tx * 8];
            ulonglong2 q1 = *(const ulonglong2*)&Bs[k][tx * 8 + 4];
            unsigned long long b0 = q0.x, b1 = q0.y, b2 = q1.x, b3 = q1.y;
            float av[8] = {a0.x, a0.y, a0.z, a0.w, a1.x, a1.y, a1.z, a1.w};
#pragma unroll
            for (int i = 0; i < 8; i++) {
                unsigned long long ap = pk2(av[i]);
                ffma2(acc[i][0], ap, b0); ffma2(acc[i][1], ap, b1);
                ffma2(acc[i][2], ap, b2); ffma2(acc[i][3], ap, b3);
            }
        }
        __syncthreads();
    }

    int nb = n0 + tx * 8;
    float4 bi0 = *(const float4*)&bih[nb];
    float4 bi1 = *(const float4*)&bih[nb + 4];
#pragma unroll
    for (int i = 0; i < 8; i++) {
        int b = ty * 8 + i;
        float* o = &d_GI[(size_t)(ts * BB + b) * G3 + nb];
        float2 c0 = up2(acc[i][0]), c1 = up2(acc[i][1]);
        float2 c2 = up2(acc[i][2]), c3 = up2(acc[i][3]);
        float4 o0 = make_float4(c0.x + bi0.x, c0.y + bi0.y, c1.x + bi0.z, c1.y + bi0.w);
        float4 o1 = make_float4(c2.x + bi1.x, c2.y + bi1.y, c3.x + bi1.z, c3.y + bi1.w);
        *(float4*)o = o0;
        *(float4*)(o + 4) = o1;
    }
}

// ---------------------------------------------------------------------------
// Kernel 3: FUSED GRU step. One launch per t (31 total, replaces 62).
// grid (32 jb, 4 bb), 256 thr. tx=tid&7 -> j-pair j0+2tx; ty=tid>>3 -> b.
// f32x2 accumulation packed over (even k, odd k): h and W smem reads are
// natural k-adjacent LDS.64. Pad 70 floats (=280B row stride): conflict-free
// reads; loaders use float2 STS (280 % 8 == 0; float4 STS would be
// misaligned on odd rows — that bug crashed round 9).
// K=512 in 8 chunks of 64 with register prefetch double-buffer.
// ---------------------------------------------------------------------------
__global__ __launch_bounds__(256) void k_step(int t, const float* __restrict__ Whh,
                                              const float* __restrict__ bhh) {
    __shared__ float Hs[32][70];   // [b][k]
    __shared__ float Ws[48][70];   // [g*16+jj][k]
    int tid = threadIdx.x;
    int tx = tid & 7, ty = tid >> 3;
    int j0 = blockIdx.x * 16, b0 = blockIdx.y * 32;
    const float* hp = d_Hseq + (size_t)t * BB * HH;

    // loader indices
    int hrow = tid >> 3, hcol = (tid & 7) * 4;      // Hs: 32 x (2 quads)
    int wrow16 = tid >> 4, wcol = (tid & 15) * 4;   // Ws: 3 x (16 x 1 quad)

    // prefetch chunk 0
    float4 ph[2], pw[3];
#pragma unroll
    for (int p = 0; p < 2; p++)
        ph[p] = *(const float4*)&hp[(size_t)(b0 + hrow) * HH + hcol + 32 * p];
#pragma unroll
    for (int i = 0; i < 3; i++)
        pw[i] = *(const float4*)&Whh[(size_t)(i * HH + j0 + wrow16) * HH + wcol];

    unsigned long long acc[3][2];
#pragma unroll
    for (int g = 0; g < 3; g++) { acc[g][0] = 0ull; acc[g][1] = 0ull; }

#pragma unroll 1
    for (int c = 0; c < 8; c++) {
        __syncthreads();
#pragma unroll
        for (int p = 0; p < 2; p++) {
            *(float2*)&Hs[hrow][hcol + 32 * p]     = make_float2(ph[p].x, ph[p].y);
            *(float2*)&Hs[hrow][hcol + 32 * p + 2] = make_float2(ph[p].z, ph[p].w);
        }
#pragma unroll
        for (int i = 0; i < 3; i++) {
            *(float2*)&Ws[i * 16 + wrow16][wcol]     = make_float2(pw[i].x, pw[i].y);
            *(float2*)&Ws[i * 16 + wrow16][wcol + 2] = make_float2(pw[i].z, pw[i].w);
        }
        __syncthreads();

        if (c < 7) {
            int k1 = (c + 1) * 64;
#pragma unroll
            for (int p = 0; p < 2; p++)
                ph[p] = *(const float4*)&hp[(size_t)(b0 + hrow) * HH + k1 + hcol + 32 * p];
#pragma unroll
            for (int i = 0; i < 3; i++)
                pw[i] = *(const float4*)&Whh[(size_t)(i * HH + j0 + wrow16) * HH + k1 + wcol];
        }

#pragma unroll
        for (int kp = 0; kp < 32; kp++) {
            unsigned long long hv = *(const unsigned long long*)&Hs[ty][2 * kp];
#pragma unroll
            for (int g = 0; g < 3; g++) {
#pragma unroll
                for (int jj = 0; jj < 2; jj++) {
                    unsigned long long wv =
                        *(const unsigned long long*)&Ws[g * 16 + 2 * tx + jj][2 * kp];
                    ffma2(acc[g][jj], hv, wv);
                }
            }
        }
    }

    // epilogue: reduce k-pairs, add b_hh, gate math, write h_{t+1}
    int b = b0 + ty;
    int j = j0 + 2 * tx;
    float2 pr0 = up2(acc[0][0]), pr1 = up2(acc[0][1]);
    float2 pz0 = up2(acc[1][0]), pz1 = up2(acc[1][1]);
    float2 pn0 = up2(acc[2][0]), pn1 = up2(acc[2][1]);
    float ghr[2] = {pr0.x + pr0.y, pr1.x + pr1.y};
    float ghz[2] = {pz0.x + pz0.y, pz1.x + pz1.y};
    float ghn[2] = {pn0.x + pn0.y, pn1.x + pn1.y};

    const float* gi = d_GI + ((size_t)t * BB + b) * G3;
    float2 gir = *(const float2*)&gi[j];
    float2 giz = *(const float2*)&gi[512 + j];
    float2 gin = *(const float2*)&gi[1024 + j];
    float2 br = *(const float2*)&bhh[j];
    float2 bz = *(const float2*)&bhh[512 + j];
    float2 bn = *(const float2*)&bhh[1024 + j];
    float2 hold = *(const float2*)&hp[(size_t)b * HH + j];

    float gir_[2] = {gir.x, gir.y}, giz_[2] = {giz.x, giz.y}, gin_[2] = {gin.x, gin.y};
    float br_[2] = {br.x, br.y}, bz_[2] = {bz.x, bz.y}, bn_[2] = {bn.x, bn.y};
    float ho_[2] = {hold.x, hold.y};
    float hn_[2];
#pragma unroll
    for (int jj = 0; jj < 2; jj++) {
        float r = 1.f / (1.f + expf(-(gir_[jj] + ghr[jj] + br_[jj])));
        float z = 1.f / (1.f + expf(-(giz_[jj] + ghz[jj] + bz_[jj])));
        float n = tanhf(gin_[jj] + r * (ghn[jj] + bn_[jj]));
        hn_[jj] = (1.f - z) * n + z * ho_[jj];
    }
    *(float2*)&d_Hseq[(size_t)(t + 1) * BB * HH + (size_t)b * HH + j] =
        make_float2(hn_[0], hn_[1]);
}

// ---------------------------------------------------------------------------
// Kernel 4: tf32 mma.sync GEMM  out[b][ts][n] = Hseq[ts+1] @ W_cls + b_cls
// CTA tile 128x128, 256 threads (8 warps, warp grid 4m x 2n, warp tile 32x64).
// K=512 in 16 serial chunks of 32 with register double-buffer prefetch.
// Bs pad 136 -> conflict-free col-fragment reads.
// grid (TT, 250): mt fast so 31 CTAs sharing a B tile are wave-adjacent (L2).
// ---------------------------------------------------------------------------
__global__ __launch_bounds__(256, 2) void k_mma(const float* __restrict__ Wc,
                                                const float* __restrict__ bcls,
                                                float* __restrict__ out) {
    __shared__ float As[128][36];    // [m][k], pad 4 -> conflict-free frags
    __shared__ float Bs[32][136];    // [k][n], pad 8 -> conflict-free frags
    int tid = threadIdx.x;
    int wid = tid >> 5, lane = tid & 31;
    int g = lane >> 2, tig = lane & 3;
    int mt = blockIdx.x, nt = blockIdx.y;
    int n0 = nt * 128;
    const float* Ab = d_Hseq + (size_t)(mt + 1) * BB * HH;   // h after step mt
    int wm = (wid & 3) * 32;        // warp M offset (4 warps along M)
    int wn = (wid >> 2) * 64;       // warp N offset (2 warps along N)

    float acc[2][8][4];             // [mi][nj][c]
#pragma unroll
    for (int mi = 0; mi < 2; mi++)
#pragma unroll
        for (int nj = 0; nj < 8; nj++)
#pragma unroll
            for (int q = 0; q < 4; q++) acc[mi][nj][q] = 0.f;

    // loaders
    int arow = tid >> 1, acolb = (tid & 1) * 16;     // A: 128 rows x 32 cols
    int brow = tid >> 3, bcolb = (tid & 7) * 4;      // B: 32 rows x 128 cols
    const float* Aptr = &Ab[(size_t)arow * HH + acolb];
    const float* Bptr = &Wc[(size_t)brow * VV + n0 + bcolb];

    // prefetch chunk 0 into registers
    float4 pa[4], pb[4];
#pragma unroll
    for (int i = 0; i < 4; i++) pa[i] = *(const float4*)&Aptr[i * 4];
#pragma unroll
    for (int i = 0; i < 4; i++) pb[i] = *(const float4*)&Bptr[32 * i];

#pragma unroll 1
    for (int c = 0; c < 16; c++) {
        __syncthreads();   // previous chunk's consumers done before overwrite
#pragma unroll
        for (int i = 0; i < 4; i++) {
            float4 v = pa[i];
            v.x = tf32r(v.x); v.y = tf32r(v.y); v.z = tf32r(v.z); v.w = tf32r(v.w);
            *(float4*)&As[arow][acolb + i * 4] = v;
        }
#pragma unroll
        for (int i = 0; i < 4; i++) {
            float4 v = pb[i];
            v.x = tf32r(v.x); v.y = tf32r(v.y); v.z = tf32r(v.z); v.w = tf32r(v.w);
            *(float4*)&Bs[brow][bcolb + 32 * i] = v;
        }
        __syncthreads();

        // issue next chunk's global loads; they complete under the compute below
        if (c < 15) {
            int k1 = (c + 1) * 32;
#pragma unroll
            for (int i = 0; i < 4; i++) pa[i] = *(const float4*)&Aptr[k1 + i * 4];
#pragma unroll
            for (int i = 0; i < 4; i++) pb[i] = *(const float4*)&Bptr[(size_t)k1 * VV + 32 * i];
        }

#pragma unroll
        for (int kk = 0; kk < 32; kk += 8) {
            uint32_t af[2][4];
#pragma unroll
            for (int mi = 0; mi < 2; mi++) {
                int m = wm + mi * 16;
                af[mi][0] = __float_as_uint(As[m + g][kk + tig]);
                af[mi][1] = __float_as_uint(As[m + g + 8][kk + tig]);
                af[mi][2] = __float_as_uint(As[m + g][kk + tig + 4]);
                af[mi][3] = __float_as_uint(As[m + g + 8][kk + tig + 4]);
            }
            uint32_t bf[8][2];
#pragma unroll
            for (int nj = 0; nj < 8; nj++) {
                int n = wn + nj * 8 + g;
                bf[nj][0] = __float_as_uint(Bs[kk + tig][n]);
                bf[nj][1] = __float_as_uint(Bs[kk + tig + 4][n]);
            }
#pragma unroll
            for (int mi = 0; mi < 2; mi++)
#pragma unroll
                for (int nj = 0; nj < 8; nj++)
                    mma8(acc[mi][nj], af[mi], bf[nj]);
        }
    }

    // epilogue: C[m][n] -> out[(m)*TT + mt][n0+n], + bias
#pragma unroll
    for (int mi = 0; mi < 2; mi++) {
        int m = wm + mi * 16;
        int r0 = m + g, r1 = m + g + 8;
        float* o0 = out + ((size_t)r0 * TT + mt) * VV + n0;
        float* o1 = out + ((size_t)r1 * TT + mt) * VV + n0;
#pragma unroll
        for (int nj = 0; nj < 8; nj++) {
            int n = wn + nj * 8 + 2 * tig;
            float2 bv = *(const float2*)&bcls[n0 + n];
            float2 v0 = make_float2(acc[mi][nj][0] + bv.x, acc[mi][nj][1] + bv.y);
            float2 v1 = make_float2(acc[mi][nj][2] + bv.x, acc[mi][nj][3] + bv.y);
            *(float2*)&o0[n] = v0;
            *(float2*)&o1[n] = v1;
        }
    }
}

// ---------------------------------------------------------------------------
extern "C" void kernel_launch(void* const* d_in, const int* in_sizes, int n_in,
                              void* d_out, int out_size) {
    const float* g_feat = (const float*)d_in[0];
    const float* t_feat = (const float*)d_in[1];
    const float* lang_feat = (const float*)d_in[2];
    // d_in[3] = lang_len (unused; T is static)
    const float* W_feat = (const float*)d_in[4];
    const float* b_feat = (const float*)d_in[5];
    const float* W_ih = (const float*)d_in[6];
    const float* W_hh = (const float*)d_in[7];
    const float* b_ih = (const float*)d_in[8];
    const float* b_hh = (const float*)d_in[9];
    const float* W_cls = (const float*)d_in[10];
    const float* b_cls = (const float*)d_in[11];
    float* out = (float*)d_out;

    // hidden0
    k_feat<<<dim3(2, BB), 256>>>(g_feat, t_feat, W_feat, b_feat);
    // all input gates at once (no recurrence)
    k_gi<<<dim3(G3 / 128, TT), 256>>>(lang_feat, W_ih, b_ih);
    // fused sequential GRU recurrence: ONE kernel per step
    for (int t = 0; t < TT; t++)
        k_step<<<dim3(32, 4), 256>>>(t, W_hh, b_hh);
    // tf32 tensor-core classifier GEMM over all timesteps (mt fast for L2 reuse)
    k_mma<<<dim3(TT, VV / 128), 256>>>(W_cls, b_cls, out);
}

// round 15
// speedup vs baseline: 1.0024x; 1.0024x over previous
#include <cuda_runtime.h>
#include <cstdint>

// Problem constants (ShowAndTell GRU decoder)
#define BB 128        // batch
#define TT 31         // decode steps (T-1)
#define EE 300        // embed dim
#define HH 512        // hidden
#define VV 32000      // vocab
#define G3 1536       // 3*H

// Scratch (static device globals; no allocation allowed)
__device__ float d_Hseq[32 * BB * HH];        // h_0 .. h_31   [t][b][h]
__device__ float d_GI[TT * BB * G3];          // input gates   [(t*B+b)][3H]

// ---------- PTX helpers (base-target safe: sm_80+ features only) ----------
static __device__ __forceinline__ float tf32r(float x) {
    uint32_t u;
    asm("cvt.rna.tf32.f32 %0, %1;" : "=r"(u) : "f"(x));
    return __uint_as_float(u);
}
// m16n8k8 tf32 MMA (legacy HMMA path; supported on base sm_103 target)
static __device__ __forceinline__ void mma8(float* c, const uint32_t* a, const uint32_t* b) {
    asm volatile(
        "mma.sync.aligned.m16n8k8.row.col.f32.tf32.tf32.f32 "
        "{%0,%1,%2,%3}, {%4,%5,%6,%7}, {%8,%9}, {%0,%1,%2,%3};"
        : "+f"(c[0]), "+f"(c[1]), "+f"(c[2]), "+f"(c[3])
        : "r"(a[0]), "r"(a[1]), "r"(a[2]), "r"(a[3]), "r"(b[0]), "r"(b[1]));
}

// ---------- packed f32x2 helpers (FFMA2 path; proven on this toolchain) ----------
static __device__ __forceinline__ unsigned long long pk2(float a) {
    unsigned long long r;
    asm("mov.b64 %0, {%1, %1};" : "=l"(r) : "f"(a));
    return r;
}
static __device__ __forceinline__ void ffma2(unsigned long long &c,
                                             unsigned long long a,
                                             unsigned long long b) {
    asm("fma.rn.f32x2 %0, %1, %2, %0;" : "+l"(c) : "l"(a), "l"(b));
}
static __device__ __forceinline__ float2 up2(unsigned long long v) {
    float2 f;
    asm("mov.b64 {%0, %1}, %2;" : "=f"(f.x), "=f"(f.y) : "l"(v));
    return f;
}

// ---------------------------------------------------------------------------
// Kernel 1: hidden0 = relu(concat(g,t) @ W_feat + b_feat)   -> d_Hseq[0]
// ---------------------------------------------------------------------------
__global__ void k_feat(const float* __restrict__ g, const float* __restrict__ t,
                       const float* __restrict__ Wf, const float* __restrict__ bf) {
    __shared__ float sg[128], st[128];
    int b = blockIdx.y;
    int j = blockIdx.x * 256 + threadIdx.x;
    if (threadIdx.x < 128) {
        sg[threadIdx.x] = g[b * 128 + threadIdx.x];
        st[threadIdx.x] = t[b * 128 + threadIdx.x];
    }
    __syncthreads();
    float acc = bf[j];
#pragma unroll 4
    for (int k = 0; k < 128; k++) acc += sg[k] * Wf[k * HH + j];
#pragma unroll 4
    for (int k = 0; k < 128; k++) acc += st[k] * Wf[(128 + k) * HH + j];
    d_Hseq[b * HH + j] = fmaxf(acc, 0.f);
}

// ---------------------------------------------------------------------------
// Kernel 2: GI = X @ W_ih^T + b_ih (all timesteps, no recurrence)
// ---------------------------------------------------------------------------
__global__ __launch_bounds__(256, 2) void k_gi(const float* __restrict__ lf,
                                               const float* __restrict__ Wih,
                                               const float* __restrict__ bih) {
    __shared__ float As[16][132];
    __shared__ float Bs[16][132];
    int tid = threadIdx.x;
    int tx = tid & 15, ty = tid >> 4;
    int n0 = blockIdx.x * 128;
    int ts = blockIdx.y;

    unsigned long long acc[8][4];
#pragma unroll
    for (int i = 0; i < 8; i++)
#pragma unroll
        for (int j = 0; j < 4; j++) acc[i][j] = 0ull;

    int lr = tid >> 2;
    int lk = (tid & 3) * 4;

#pragma unroll 1
    for (int k0 = 0; k0 < EE; k0 += 16) {
        bool kok = (k0 + lk) < EE;
#pragma unroll
        for (int p = 0; p < 2; p++) {
            int r = lr + p * 64;
            float4 v = make_float4(0.f, 0.f, 0.f, 0.f);
            float4 w = make_float4(0.f, 0.f, 0.f, 0.f);
            if (kok) {
                v = *(const float4*)&lf[(size_t)(r * 32 + ts) * EE + k0 + lk];
                w = *(const float4*)&Wih[(size_t)(n0 + r) * EE + k0 + lk];
            }
            As[lk + 0][r] = v.x; As[lk + 1][r] = v.y; As[lk + 2][r] = v.z; As[lk + 3][r] = v.w;
            Bs[lk + 0][r] = w.x; Bs[lk + 1][r] = w.y; Bs[lk + 2][r] = w.z; Bs[lk + 3][r] = w.w;
        }
        __syncthreads();
#pragma unroll
        for (int k = 0; k < 16; k++) {
            float4 a0 = *(const float4*)&As[k][ty * 8];
            float4 a1 = *(const float4*)&As[k][ty * 8 + 4];
            ulonglong2 q0 = *(const ulonglong2*)&Bs[k][tx * 8];
            ulonglong2 q1 = *(const ulonglong2*)&Bs[k][tx * 8 + 4];
            unsigned long long b0 = q0.x, b1 = q0.y, b2 = q1.x, b3 = q1.y;
            float av[8] = {a0.x, a0.y, a0.z, a0.w, a1.x, a1.y, a1.z, a1.w};
#pragma unroll
            for (int i = 0; i < 8; i++) {
                unsigned long long ap = pk2(av[i]);
                ffma2(acc[i][0], ap, b0); ffma2(acc[i][1], ap, b1);
                ffma2(acc[i][2], ap, b2); ffma2(acc[i][3], ap, b3);
            }
        }
        __syncthreads();
    }

    int nb = n0 + tx * 8;
    float4 bi0 = *(const float4*)&bih[nb];
    float4 bi1 = *(const float4*)&bih[nb + 4];
#pragma unroll
    for (int i = 0; i < 8; i++) {
        int b = ty * 8 + i;
        float* o = &d_GI[(size_t)(ts * BB + b) * G3 + nb];
        float2 c0 = up2(acc[i][0]), c1 = up2(acc[i][1]);
        float2 c2 = up2(acc[i][2]), c3 = up2(acc[i][3]);
        float4 o0 = make_float4(c0.x + bi0.x, c0.y + bi0.y, c1.x + bi0.z, c1.y + bi0.w);
        float4 o1 = make_float4(c2.x + bi1.x, c2.y + bi1.y, c3.x + bi1.z, c3.y + bi1.w);
        *(float4*)o = o0;
        *(float4*)(o + 4) = o1;
    }
}

// ---------------------------------------------------------------------------
// Kernel 3: FUSED GRU step. One launch per t (31 total, replaces 62).
// grid (32 jb, 4 bb), 256 thr. tx=tid&7 -> j-pair j0+2tx; ty=tid>>3 -> b.
// f32x2 accumulation packed over (even k, odd k): h and W smem reads are
// natural k-adjacent LDS.64.
// Shared tiles are NATIVE float2 arrays ([32][35] / [48][35] = same 280-byte
// row stride as the old padded-70-float layout, same conflict-free banking)
// so 8-byte alignment of every STS.64/LDS.64 is guaranteed by the type —
// the raw-float versions relied on unguaranteed base alignment.
// K=512 in 8 chunks of 64 with register prefetch double-buffer.
// ---------------------------------------------------------------------------
__global__ __launch_bounds__(256) void k_step(int t, const float* __restrict__ Whh,
                                              const float* __restrict__ bhh) {
    __shared__ float2 Hs[32][35];   // [b][k-pair], row = 280 B
    __shared__ float2 Ws[48][35];   // [g*16+jj][k-pair]
    int tid = threadIdx.x;
    int tx = tid & 7, ty = tid >> 3;
    int j0 = blockIdx.x * 16, b0 = blockIdx.y * 32;
    const float* hp = d_Hseq + (size_t)t * BB * HH;

    // loader indices (float2 units; *2 = float column)
    int hrow = tid >> 3, hc2 = (tid & 7) * 2;       // Hs: 32 rows x 2 quads
    int wrow16 = tid >> 4, wc2 = (tid & 15) * 2;    // Ws: 3 x (16 rows x 1 quad)

    // prefetch chunk 0
    float4 ph[2], pw[3];
#pragma unroll
    for (int p = 0; p < 2; p++)
        ph[p] = *(const float4*)&hp[(size_t)(b0 + hrow) * HH + hc2 * 2 + 32 * p];
#pragma unroll
    for (int i = 0; i < 3; i++)
        pw[i] = *(const float4*)&Whh[(size_t)(i * HH + j0 + wrow16) * HH + wc2 * 2];

    unsigned long long acc[3][2];
#pragma unroll
    for (int g = 0; g < 3; g++) { acc[g][0] = 0ull; acc[g][1] = 0ull; }

#pragma unroll 1
    for (int c = 0; c < 8; c++) {
        __syncthreads();
#pragma unroll
        for (int p = 0; p < 2; p++) {
            Hs[hrow][hc2 + 16 * p]     = make_float2(ph[p].x, ph[p].y);
            Hs[hrow][hc2 + 16 * p + 1] = make_float2(ph[p].z, ph[p].w);
        }
#pragma unroll
        for (int i = 0; i < 3; i++) {
            Ws[i * 16 + wrow16][wc2]     = make_float2(pw[i].x, pw[i].y);
            Ws[i * 16 + wrow16][wc2 + 1] = make_float2(pw[i].z, pw[i].w);
        }
        __syncthreads();

        if (c < 7) {
            int k1 = (c + 1) * 64;
#pragma unroll
            for (int p = 0; p < 2; p++)
                ph[p] = *(const float4*)&hp[(size_t)(b0 + hrow) * HH + k1 + hc2 * 2 + 32 * p];
#pragma unroll
            for (int i = 0; i < 3; i++)
                pw[i] = *(const float4*)&Whh[(size_t)(i * HH + j0 + wrow16) * HH + k1 + wc2 * 2];
        }

#pragma unroll
        for (int kp = 0; kp < 32; kp++) {
            unsigned long long hv = *(const unsigned long long*)&Hs[ty][kp];
#pragma unroll
            for (int g = 0; g < 3; g++) {
#pragma unroll
                for (int jj = 0; jj < 2; jj++) {
                    unsigned long long wv =
                        *(const unsigned long long*)&Ws[g * 16 + 2 * tx + jj][kp];
                    ffma2(acc[g][jj], hv, wv);
                }
            }
        }
    }

    // epilogue: reduce k-pairs, add b_hh, gate math, write h_{t+1}
    int b = b0 + ty;
    int j = j0 + 2 * tx;
    float2 pr0 = up2(acc[0][0]), pr1 = up2(acc[0][1]);
    float2 pz0 = up2(acc[1][0]), pz1 = up2(acc[1][1]);
    float2 pn0 = up2(acc[2][0]), pn1 = up2(acc[2][1]);
    float ghr[2] = {pr0.x + pr0.y, pr1.x + pr1.y};
    float ghz[2] = {pz0.x + pz0.y, pz1.x + pz1.y};
    float ghn[2] = {pn0.x + pn0.y, pn1.x + pn1.y};

    const float* gi = d_GI + ((size_t)t * BB + b) * G3;
    float2 gir = *(const float2*)&gi[j];
    float2 giz = *(const float2*)&gi[512 + j];
    float2 gin = *(const float2*)&gi[1024 + j];
    float2 br = *(const float2*)&bhh[j];
    float2 bz = *(const float2*)&bhh[512 + j];
    float2 bn = *(const float2*)&bhh[1024 + j];
    float2 hold = *(const float2*)&hp[(size_t)b * HH + j];

    float gir_[2] = {gir.x, gir.y}, giz_[2] = {giz.x, giz.y}, gin_[2] = {gin.x, gin.y};
    float br_[2] = {br.x, br.y}, bz_[2] = {bz.x, bz.y}, bn_[2] = {bn.x, bn.y};
    float ho_[2] = {hold.x, hold.y};
    float hn_[2];
#pragma unroll
    for (int jj = 0; jj < 2; jj++) {
        float r = 1.f / (1.f + expf(-(gir_[jj] + ghr[jj] + br_[jj])));
        float z = 1.f / (1.f + expf(-(giz_[jj] + ghz[jj] + bz_[jj])));
        float n = tanhf(gin_[jj] + r * (ghn[jj] + bn_[jj]));
        hn_[jj] = (1.f - z) * n + z * ho_[jj];
    }
    *(float2*)&d_Hseq[(size_t)(t + 1) * BB * HH + (size_t)b * HH + j] =
        make_float2(hn_[0], hn_[1]);
}

// ---------------------------------------------------------------------------
// Kernel 4: tf32 mma.sync GEMM  out[b][ts][n] = Hseq[ts+1] @ W_cls + b_cls
// CTA tile 128x128, 256 threads (8 warps, warp grid 4m x 2n, warp tile 32x64).
// K=512 in 16 serial chunks of 32 with register double-buffer prefetch.
// Bs pad 136 -> conflict-free col-fragment reads.
// grid (TT, 250): mt fast so 31 CTAs sharing a B tile are wave-adjacent (L2).
// ---------------------------------------------------------------------------
__global__ __launch_bounds__(256, 2) void k_mma(const float* __restrict__ Wc,
                                                const float* __restrict__ bcls,
                                                float* __restrict__ out) {
    __shared__ float As[128][36];    // [m][k], pad 4 -> conflict-free frags
    __shared__ float Bs[32][136];    // [k][n], pad 8 -> conflict-free frags
    int tid = threadIdx.x;
    int wid = tid >> 5, lane = tid & 31;
    int g = lane >> 2, tig = lane & 3;
    int mt = blockIdx.x, nt = blockIdx.y;
    int n0 = nt * 128;
    const float* Ab = d_Hseq + (size_t)(mt + 1) * BB * HH;   // h after step mt
    int wm = (wid & 3) * 32;        // warp M offset (4 warps along M)
    int wn = (wid >> 2) * 64;       // warp N offset (2 warps along N)

    float acc[2][8][4];             // [mi][nj][c]
#pragma unroll
    for (int mi = 0; mi < 2; mi++)
#pragma unroll
        for (int nj = 0; nj < 8; nj++)
#pragma unroll
            for (int q = 0; q < 4; q++) acc[mi][nj][q] = 0.f;

    // loaders
    int arow = tid >> 1, acolb = (tid & 1) * 16;     // A: 128 rows x 32 cols
    int brow = tid >> 3, bcolb = (tid & 7) * 4;      // B: 32 rows x 128 cols
    const float* Aptr = &Ab[(size_t)arow * HH + acolb];
    const float* Bptr = &Wc[(size_t)brow * VV + n0 + bcolb];

    // prefetch chunk 0 into registers
    float4 pa[4], pb[4];
#pragma unroll
    for (int i = 0; i < 4; i++) pa[i] = *(const float4*)&Aptr[i * 4];
#pragma unroll
    for (int i = 0; i < 4; i++) pb[i] = *(const float4*)&Bptr[32 * i];

#pragma unroll 1
    for (int c = 0; c < 16; c++) {
        __syncthreads();   // previous chunk's consumers done before overwrite
#pragma unroll
        for (int i = 0; i < 4; i++) {
            float4 v = pa[i];
            v.x = tf32r(v.x); v.y = tf32r(v.y); v.z = tf32r(v.z); v.w = tf32r(v.w);
            *(float4*)&As[arow][acolb + i * 4] = v;
        }
#pragma unroll
        for (int i = 0; i < 4; i++) {
            float4 v = pb[i];
            v.x = tf32r(v.x); v.y = tf32r(v.y); v.z = tf32r(v.z); v.w = tf32r(v.w);
            *(float4*)&Bs[brow][bcolb + 32 * i] = v;
        }
        __syncthreads();

        // issue next chunk's global loads; they complete under the compute below
        if (c < 15) {
            int k1 = (c + 1) * 32;
#pragma unroll
            for (int i = 0; i < 4; i++) pa[i] = *(const float4*)&Aptr[k1 + i * 4];
#pragma unroll
            for (int i = 0; i < 4; i++) pb[i] = *(const float4*)&Bptr[(size_t)k1 * VV + 32 * i];
        }

#pragma unroll
        for (int kk = 0; kk < 32; kk += 8) {
            uint32_t af[2][4];
#pragma unroll
            for (int mi = 0; mi < 2; mi++) {
                int m = wm + mi * 16;
                af[mi][0] = __float_as_uint(As[m + g][kk + tig]);
                af[mi][1] = __float_as_uint(As[m + g + 8][kk + tig]);
                af[mi][2] = __float_as_uint(As[m + g][kk + tig + 4]);
                af[mi][3] = __float_as_uint(As[m + g + 8][kk + tig + 4]);
            }
            uint32_t bf[8][2];
#pragma unroll
            for (int nj = 0; nj < 8; nj++) {
                int n = wn + nj * 8 + g;
                bf[nj][0] = __float_as_uint(Bs[kk + tig][n]);
                bf[nj][1] = __float_as_uint(Bs[kk + tig + 4][n]);
            }
#pragma unroll
            for (int mi = 0; mi < 2; mi++)
#pragma unroll
                for (int nj = 0; nj < 8; nj++)
                    mma8(acc[mi][nj], af[mi], bf[nj]);
        }
    }

    // epilogue: C[m][n] -> out[(m)*TT + mt][n0+n], + bias
#pragma unroll
    for (int mi = 0; mi < 2; mi++) {
        int m = wm + mi * 16;
        int r0 = m + g, r1 = m + g + 8;
        float* o0 = out + ((size_t)r0 * TT + mt) * VV + n0;
        float* o1 = out + ((size_t)r1 * TT + mt) * VV + n0;
#pragma unroll
        for (int nj = 0; nj < 8; nj++) {
            int n = wn + nj * 8 + 2 * tig;
            float2 bv = *(const float2*)&bcls[n0 + n];
            float2 v0 = make_float2(acc[mi][nj][0] + bv.x, acc[mi][nj][1] + bv.y);
            float2 v1 = make_float2(acc[mi][nj][2] + bv.x, acc[mi][nj][3] + bv.y);
            *(float2*)&o0[n] = v0;
            *(float2*)&o1[n] = v1;
        }
    }
}

// ---------------------------------------------------------------------------
extern "C" void kernel_launch(void* const* d_in, const int* in_sizes, int n_in,
                              void* d_out, int out_size) {
    const float* g_feat = (const float*)d_in[0];
    const float* t_feat = (const float*)d_in[1];
    const float* lang_feat = (const float*)d_in[2];
    // d_in[3] = lang_len (unused; T is static)
    const float* W_feat = (const float*)d_in[4];
    const float* b_feat = (const float*)d_in[5];
    const float* W_ih = (const float*)d_in[6];
    const float* W_hh = (const float*)d_in[7];
    const float* b_ih = (const float*)d_in[8];
    const float* b_hh = (const float*)d_in[9];
    const float* W_cls = (const float*)d_in[10];
    const float* b_cls = (const float*)d_in[11];
    float* out = (float*)d_out;

    // hidden0
    k_feat<<<dim3(2, BB), 256>>>(g_feat, t_feat, W_feat, b_feat);
    // all input gates at once (no recurrence)
    k_gi<<<dim3(G3 / 128, TT), 256>>>(lang_feat, W_ih, b_ih);
    // fused sequential GRU recurrence: ONE kernel per step
    for (int t = 0; t < TT; t++)
        k_step<<<dim3(32, 4), 256>>>(t, W_hh, b_hh);
    // tf32 tensor-core classifier GEMM over all timesteps (mt fast for L2 reuse)
    k_mma<<<dim3(TT, VV / 128), 256>>>(W_cls, b_cls, out);
}

// round 16
// speedup vs baseline: 1.1985x; 1.1955x over previous
#include <cuda_runtime.h>
#include <cuda_fp16.h>
#include <cstdint>

// Problem constants (ShowAndTell GRU decoder)
#define BB 128        // batch
#define TT 31         // decode steps (T-1)
#define EE 300        // embed dim
#define HH 512        // hidden
#define VV 32000      // vocab
#define G3 1536       // 3*H
#define KSPLIT 8      // K-split for recurrent GEMM

// Scratch (static device globals; no allocation allowed)
__device__ float d_Hseq[32 * BB * HH];        // h_0 .. h_31   [t][b][h]
__device__ float d_GI[TT * BB * G3];          // input gates   [(t*B+b)][3H]
__device__ float d_GHpart[KSPLIT * BB * G3];  // split-K partials of h @ W_hh^T

// ---------- PTX helpers (base-target safe: sm_80+ features only) ----------
// fp16 m16n8k16 MMA (HMMA; supported on base sm_103 target)
static __device__ __forceinline__ void mma16(float* c, const uint32_t* a, const uint32_t* b) {
    asm volatile(
        "mma.sync.aligned.m16n8k16.row.col.f32.f16.f16.f32 "
        "{%0,%1,%2,%3}, {%4,%5,%6,%7}, {%8,%9}, {%0,%1,%2,%3};"
        : "+f"(c[0]), "+f"(c[1]), "+f"(c[2]), "+f"(c[3])
        : "r"(a[0]), "r"(a[1]), "r"(a[2]), "r"(a[3]), "r"(b[0]), "r"(b[1]));
}
static __device__ __forceinline__ void ldsm_x4(uint32_t* r, uint32_t addr) {
    asm volatile("ldmatrix.sync.aligned.m8n8.x4.shared.b16 {%0,%1,%2,%3}, [%4];"
                 : "=r"(r[0]), "=r"(r[1]), "=r"(r[2]), "=r"(r[3]) : "r"(addr));
}
static __device__ __forceinline__ void ldsm_x2_t(uint32_t* r, uint32_t addr) {
    asm volatile("ldmatrix.sync.aligned.m8n8.x2.trans.shared.b16 {%0,%1}, [%2];"
                 : "=r"(r[0]), "=r"(r[1]) : "r"(addr));
}
static __device__ __forceinline__ uint32_t h2pack(float x, float y) {
    __half2 h = __floats2half2_rn(x, y);
    return *(uint32_t*)&h;
}

// ---------- packed f32x2 helpers (FFMA2 path; proven on this toolchain) ----------
static __device__ __forceinline__ unsigned long long pk2(float a) {
    unsigned long long r;
    asm("mov.b64 %0, {%1, %1};" : "=l"(r) : "f"(a));
    return r;
}
static __device__ __forceinline__ void ffma2(unsigned long long &c,
                                             unsigned long long a,
                                             unsigned long long b) {
    asm("fma.rn.f32x2 %0, %1, %2, %0;" : "+l"(c) : "l"(a), "l"(b));
}
static __device__ __forceinline__ float2 up2(unsigned long long v) {
    float2 f;
    asm("mov.b64 {%0, %1}, %2;" : "=f"(f.x), "=f"(f.y) : "l"(v));
    return f;
}

// ---------------------------------------------------------------------------
// Kernel 1: hidden0 = relu(concat(g,t) @ W_feat + b_feat)   -> d_Hseq[0]
// ---------------------------------------------------------------------------
__global__ void k_feat(const float* __restrict__ g, const float* __restrict__ t,
                       const float* __restrict__ Wf, const float* __restrict__ bf) {
    __shared__ float sg[128], st[128];
    int b = blockIdx.y;
    int j = blockIdx.x * 256 + threadIdx.x;
    if (threadIdx.x < 128) {
        sg[threadIdx.x] = g[b * 128 + threadIdx.x];
        st[threadIdx.x] = t[b * 128 + threadIdx.x];
    }
    __syncthreads();
    float acc = bf[j];
#pragma unroll 4
    for (int k = 0; k < 128; k++) acc += sg[k] * Wf[k * HH + j];
#pragma unroll 4
    for (int k = 0; k < 128; k++) acc += st[k] * Wf[(128 + k) * HH + j];
    d_Hseq[b * HH + j] = fmaxf(acc, 0.f);
}

// ---------------------------------------------------------------------------
// Kernel 2: GI = X @ W_ih^T + b_ih (all timesteps, no recurrence)
// ---------------------------------------------------------------------------
__global__ __launch_bounds__(256, 2) void k_gi(const float* __restrict__ lf,
                                               const float* __restrict__ Wih,
                                               const float* __restrict__ bih) {
    __shared__ float As[16][132];
    __shared__ float Bs[16][132];
    int tid = threadIdx.x;
    int tx = tid & 15, ty = tid >> 4;
    int n0 = blockIdx.x * 128;
    int ts = blockIdx.y;

    unsigned long long acc[8][4];
#pragma unroll
    for (int i = 0; i < 8; i++)
#pragma unroll
        for (int j = 0; j < 4; j++) acc[i][j] = 0ull;

    int lr = tid >> 2;
    int lk = (tid & 3) * 4;

#pragma unroll 1
    for (int k0 = 0; k0 < EE; k0 += 16) {
        bool kok = (k0 + lk) < EE;
#pragma unroll
        for (int p = 0; p < 2; p++) {
            int r = lr + p * 64;
            float4 v = make_float4(0.f, 0.f, 0.f, 0.f);
            float4 w = make_float4(0.f, 0.f, 0.f, 0.f);
            if (kok) {
                v = *(const float4*)&lf[(size_t)(r * 32 + ts) * EE + k0 + lk];
                w = *(const float4*)&Wih[(size_t)(n0 + r) * EE + k0 + lk];
            }
            As[lk + 0][r] = v.x; As[lk + 1][r] = v.y; As[lk + 2][r] = v.z; As[lk + 3][r] = v.w;
            Bs[lk + 0][r] = w.x; Bs[lk + 1][r] = w.y; Bs[lk + 2][r] = w.z; Bs[lk + 3][r] = w.w;
        }
        __syncthreads();
#pragma unroll
        for (int k = 0; k < 16; k++) {
            float4 a0 = *(const float4*)&As[k][ty * 8];
            float4 a1 = *(const float4*)&As[k][ty * 8 + 4];
            ulonglong2 q0 = *(const ulonglong2*)&Bs[k][tx * 8];
            ulonglong2 q1 = *(const ulonglong2*)&Bs[k][tx * 8 + 4];
            unsigned long long b0 = q0.x, b1 = q0.y, b2 = q1.x, b3 = q1.y;
            float av[8] = {a0.x, a0.y, a0.z, a0.w, a1.x, a1.y, a1.z, a1.w};
#pragma unroll
            for (int i = 0; i < 8; i++) {
                unsigned long long ap = pk2(av[i]);
                ffma2(acc[i][0], ap, b0); ffma2(acc[i][1], ap, b1);
                ffma2(acc[i][2], ap, b2); ffma2(acc[i][3], ap, b3);
            }
        }
        __syncthreads();
    }

    int nb = n0 + tx * 8;
    float4 bi0 = *(const float4*)&bih[nb];
    float4 bi1 = *(const float4*)&bih[nb + 4];
#pragma unroll
    for (int i = 0; i < 8; i++) {
        int b = ty * 8 + i;
        float* o = &d_GI[(size_t)(ts * BB + b) * G3 + nb];
        float2 c0 = up2(acc[i][0]), c1 = up2(acc[i][1]);
        float2 c2 = up2(acc[i][2]), c3 = up2(acc[i][3]);
        float4 o0 = make_float4(c0.x + bi0.x, c0.y + bi0.y, c1.x + bi0.z, c1.y + bi0.w);
        float4 o1 = make_float4(c2.x + bi1.x, c2.y + bi1.y, c3.x + bi1.z, c3.y + bi1.w);
        *(float4*)o = o0;
        *(float4*)(o + 4) = o1;
    }
}

// ---------------------------------------------------------------------------
// Kernel 3a: split-K GEMM  GHpart[ks] = h_t @ W_hh^T   (proven config)
// ---------------------------------------------------------------------------
__global__ __launch_bounds__(256) void k_gh(int t, const float* __restrict__ Whh) {
    __shared__ float As[16][132];
    __shared__ float Bs[16][68];
    int tid = threadIdx.x;
    int tx = tid & 15, ty = tid >> 4;
    int n0 = blockIdx.x * 64;
    int kbase = blockIdx.y * 64;
    const float* hp = d_Hseq + (size_t)t * BB * HH;

    float acc[8][4];
#pragma unroll
    for (int i = 0; i < 8; i++)
#pragma unroll
        for (int j = 0; j < 4; j++) acc[i][j] = 0.f;

    int lr = tid >> 2, lk = (tid & 3) * 4;

#pragma unroll 1
    for (int kc = 0; kc < 64; kc += 16) {
        int k0 = kbase + kc;
#pragma unroll
        for (int p = 0; p < 2; p++) {
            int b = lr + p * 64;
            float4 v = *(const float4*)&hp[(size_t)b * HH + k0 + lk];
            As[lk + 0][b] = v.x; As[lk + 1][b] = v.y; As[lk + 2][b] = v.z; As[lk + 3][b] = v.w;
        }
        {
            float4 w = *(const float4*)&Whh[(size_t)(n0 + lr) * HH + k0 + lk];
            Bs[lk + 0][lr] = w.x; Bs[lk + 1][lr] = w.y; Bs[lk + 2][lr] = w.z; Bs[lk + 3][lr] = w.w;
        }
        __syncthreads();
#pragma unroll
        for (int k = 0; k < 16; k++) {
            float4 a0 = *(const float4*)&As[k][ty * 8];
            float4 a1 = *(const float4*)&As[k][ty * 8 + 4];
            float4 bv = *(const float4*)&Bs[k][tx * 4];
            float av[8] = {a0.x, a0.y, a0.z, a0.w, a1.x, a1.y, a1.z, a1.w};
#pragma unroll
            for (int i = 0; i < 8; i++) {
                acc[i][0] += av[i] * bv.x;
                acc[i][1] += av[i] * bv.y;
                acc[i][2] += av[i] * bv.z;
                acc[i][3] += av[i] * bv.w;
            }
        }
        __syncthreads();
    }
#pragma unroll
    for (int i = 0; i < 8; i++) {
        int b = ty * 8 + i;
        *(float4*)&d_GHpart[(size_t)(blockIdx.y * BB + b) * G3 + n0 + tx * 4] =
            make_float4(acc[i][0], acc[i][1], acc[i][2], acc[i][3]);
    }
}

// ---------------------------------------------------------------------------
// Kernel 3b: reduce split-K partials + GRU gate math -> d_Hseq[t+1]
// ---------------------------------------------------------------------------
__global__ void k_gate(int t, const float* __restrict__ bhh) {
    int idx = blockIdx.x * 256 + threadIdx.x;
    int b = idx >> 9, j = idx & 511;

    float ghr = bhh[j], ghz = bhh[512 + j], ghn = bhh[1024 + j];
#pragma unroll
    for (int ks = 0; ks < KSPLIT; ks++) {
        const float* p = d_GHpart + (size_t)(ks * BB + b) * G3;
        ghr += p[j];
        ghz += p[512 + j];
        ghn += p[1024 + j];
    }
    const float* gi = d_GI + (size_t)(t * BB + b) * G3;
    float gir = gi[j], giz = gi[512 + j], gin = gi[1024 + j];

    float r = 1.f / (1.f + expf(-(gir + ghr)));
    float z = 1.f / (1.f + expf(-(giz + ghz)));
    float n = tanhf(gin + r * ghn);
    float hp = d_Hseq[(size_t)t * BB * HH + idx];
    d_Hseq[(size_t)(t + 1) * BB * HH + idx] = (1.f - z) * n + z * hp;
}

// ---------------------------------------------------------------------------
// Kernel 4: fp16 mma.sync GEMM  out[b][ts][n] = Hseq[ts+1] @ W_cls + b_cls
// CTA 128x128, 256 thr (8 warps, 4m x 2n, warp tile 32x64). K=512, 16 chunks
// of 32, register prefetch (converted to half2 early to save regs).
// m16n8k16 f16 (K=16/instr — half the HMMA count of the tf32 K=8 version).
// Fragments via ldmatrix: x4 for A (row-major), x2.trans for B (row-major
// smem [k][n] -> col-major frag). Strides: As row 80B (banks 20l: perfect
// 32-bank spread), Bs row 272B (banks 4l: perfect).
// grid (TT, 250): mt fast so 31 CTAs sharing a B tile are wave-adjacent (L2).
// ---------------------------------------------------------------------------
__global__ __launch_bounds__(256, 2) void k_mma(const float* __restrict__ Wc,
                                                const float* __restrict__ bcls,
                                                float* __restrict__ out) {
    __shared__ __align__(16) __half As[128][40];    // [m][k]: 32 data + 8 pad
    __shared__ __align__(16) __half Bs[32][136];    // [k][n]: 128 data + 8 pad
    int tid = threadIdx.x;
    int wid = tid >> 5, lane = tid & 31;
    int g = lane >> 2, tig = lane & 3;
    int mt = blockIdx.x, nt = blockIdx.y;
    int n0 = nt * 128;
    const float* Ab = d_Hseq + (size_t)(mt + 1) * BB * HH;   // h after step mt
    int wm = (wid & 3) * 32;        // warp M offset (4 warps along M)
    int wn = (wid >> 2) * 64;       // warp N offset (2 warps along N)

    float acc[2][8][4];
#pragma unroll
    for (int mi = 0; mi < 2; mi++)
#pragma unroll
        for (int nj = 0; nj < 8; nj++)
#pragma unroll
            for (int q = 0; q < 4; q++) acc[mi][nj][q] = 0.f;

    // loaders: per chunk each thread moves 16 A floats + 16 B floats
    int arow = tid >> 1, acolb = (tid & 1) * 16;     // A: 128 rows x 32 cols
    int brow = tid >> 3, bcolb = (tid & 7) * 16;     // B: 32 rows x 128 cols
    const float* Aptr = &Ab[(size_t)arow * HH + acolb];
    const float* Bptr = &Wc[(size_t)brow * VV + n0 + bcolb];

    // ldmatrix shared-space addresses
    uint32_t asBase = (uint32_t)__cvta_generic_to_shared(&As[0][0]);
    uint32_t bsBase = (uint32_t)__cvta_generic_to_shared(&Bs[0][0]);
    // A x4: lanes 0-7 rows m..m+7 col k0; 8-15 rows m+8..15 col k0;
    //       16-23 rows m..m+7 col k0+8; 24-31 rows m+8..15 col k0+8
    uint32_t aAddr = asBase + (uint32_t)(wm + (lane & 15)) * 80u + ((lane >> 4) * 16u);
    // B x2.trans: lanes 0-15 rows k..k+15 at col wn
    uint32_t bAddr = bsBase + (uint32_t)(lane & 15) * 272u + (uint32_t)wn * 2u;

    // prefetch chunk 0, converting to half2 immediately (register economy)
    uint32_t pa[8], pb[8];
#pragma unroll
    for (int i = 0; i < 4; i++) {
        float4 v = *(const float4*)&Aptr[i * 4];
        pa[2 * i]     = h2pack(v.x, v.y);
        pa[2 * i + 1] = h2pack(v.z, v.w);
        float4 w = *(const float4*)&Bptr[i * 4];
        pb[2 * i]     = h2pack(w.x, w.y);
        pb[2 * i + 1] = h2pack(w.z, w.w);
    }

#pragma unroll 1
    for (int c = 0; c < 16; c++) {
        __syncthreads();   // previous chunk's consumers done before overwrite
        *(uint4*)&As[arow][acolb]     = make_uint4(pa[0], pa[1], pa[2], pa[3]);
        *(uint4*)&As[arow][acolb + 8] = make_uint4(pa[4], pa[5], pa[6], pa[7]);
        *(uint4*)&Bs[brow][bcolb]     = make_uint4(pb[0], pb[1], pb[2], pb[3]);
        *(uint4*)&Bs[brow][bcolb + 8] = make_uint4(pb[4], pb[5], pb[6], pb[7]);
        __syncthreads();

        // issue next chunk's global loads; convert under the compute below
        if (c < 15) {
            int k1 = (c + 1) * 32;
#pragma unroll
            for (int i = 0; i < 4; i++) {
                float4 v = *(const float4*)&Aptr[k1 + i * 4];
                pa[2 * i]     = h2pack(v.x, v.y);
                pa[2 * i + 1] = h2pack(v.z, v.w);
                float4 w = *(const float4*)&Bptr[(size_t)k1 * VV + i * 4];
                pb[2 * i]     = h2pack(w.x, w.y);
                pb[2 * i + 1] = h2pack(w.z, w.w);
            }
        }

#pragma unroll
        for (int ks = 0; ks < 2; ks++) {
            uint32_t af[2][4];
#pragma unroll
            for (int mi = 0; mi < 2; mi++)
                ldsm_x4(af[mi], aAddr + (uint32_t)mi * (16u * 80u) + (uint32_t)ks * 32u);
#pragma unroll
            for (int nj = 0; nj < 8; nj++) {
                uint32_t bf[2];
                ldsm_x2_t(bf, bAddr + (uint32_t)ks * (16u * 272u) + (uint32_t)nj * 16u);
                mma16(acc[0][nj], af[0], bf);
                mma16(acc[1][nj], af[1], bf);
            }
        }
    }

    // epilogue: C[m][n] -> out[(m)*TT + mt][n0+n], + bias
    // c frag: c0,c1 = (row g, cols 2tig,2tig+1); c2,c3 = (row g+8, same cols)
#pragma unroll
    for (int mi = 0; mi < 2; mi++) {
        int m = wm + mi * 16;
        int r0 = m + g, r1 = m + g + 8;
        float* o0 = out + ((size_t)r0 * TT + mt) * VV + n0;
        float* o1 = out + ((size_t)r1 * TT + mt) * VV + n0;
#pragma unroll
        for (int nj = 0; nj < 8; nj++) {
            int n = wn + nj * 8 + 2 * tig;
            float2 bv = *(const float2*)&bcls[n0 + n];
            float2 v0 = make_float2(acc[mi][nj][0] + bv.x, acc[mi][nj][1] + bv.y);
            float2 v1 = make_float2(acc[mi][nj][2] + bv.x, acc[mi][nj][3] + bv.y);
            *(float2*)&o0[n] = v0;
            *(float2*)&o1[n] = v1;
        }
    }
}

// ---------------------------------------------------------------------------
extern "C" void kernel_launch(void* const* d_in, const int* in_sizes, int n_in,
                              void* d_out, int out_size) {
    const float* g_feat = (const float*)d_in[0];
    const float* t_feat = (const float*)d_in[1];
    const float* lang_feat = (const float*)d_in[2];
    // d_in[3] = lang_len (unused; T is static)
    const float* W_feat = (const float*)d_in[4];
    const float* b_feat = (const float*)d_in[5];
    const float* W_ih = (const float*)d_in[6];
    const float* W_hh = (const float*)d_in[7];
    const float* b_ih = (const float*)d_in[8];
    const float* b_hh = (const float*)d_in[9];
    const float* W_cls = (const float*)d_in[10];
    const float* b_cls = (const float*)d_in[11];
    float* out = (float*)d_out;

    // hidden0
    k_feat<<<dim3(2, BB), 256>>>(g_feat, t_feat, W_feat, b_feat);
    // all input gates at once (no recurrence)
    k_gi<<<dim3(G3 / 128, TT), 256>>>(lang_feat, W_ih, b_ih);
    // sequential GRU recurrence (proven split-K + gate pair)
    for (int t = 0; t < TT; t++) {
        k_gh<<<dim3(G3 / 64, KSPLIT), 256>>>(t, W_hh);
        k_gate<<<dim3(BB * HH / 256), 256>>>(t, b_hh);
    }
    // fp16 tensor-core classifier GEMM over all timesteps (mt fast for L2 reuse)
    k_mma<<<dim3(TT, VV / 128), 256>>>(W_cls, b_cls, out);
}